// round 2
// baseline (speedup 1.0000x reference)
#include <cuda_runtime.h>

// ---------------- problem constants ----------------
#define HDIM 96
#define CH   256
#define NB   4
#define PLANE (HDIM*HDIM)       // 9216
#define CHW   (CH*PLANE)        // 2359296

// scratch: embeddings in NCHW [B][C][H][W]
__device__ float g_Et[NB*CHW];
__device__ float g_Ee[NB*CHW];

// ---------------- f32x2 helpers ----------------
typedef unsigned long long ull;
__device__ __forceinline__ ull pack2(float x, float y){
    ull r; asm("mov.b64 %0, {%1,%2};" : "=l"(r) : "f"(x), "f"(y)); return r;
}
__device__ __forceinline__ ull fma2(ull a, ull b, ull c){
    ull r; asm("fma.rn.f32x2 %0, %1, %2, %3;" : "=l"(r) : "l"(a), "l"(b), "l"(c)); return r;
}
__device__ __forceinline__ float2 unpack2(ull v){
    float2 f; asm("mov.b64 {%0,%1}, %2;" : "=f"(f.x), "=f"(f.y) : "l"(v)); return f;
}

// =====================================================================
// Kernel 1: fused dual SGEMM (1x1 conv embeddings)
//   Out[o][p] = sum_c W[o][c] * X[c][p] + bias[o]   per batch, per matrix
//   M=256 (o), N=9216 (p, contiguous), K=256 (c)
//   BM=128, BN=128, BK=16, 256 threads, 8x8 micro-tile, f32x2 FMA.
//   A tile stored in smem pre-duplicated as (a,a) f32x2 pairs.
// =====================================================================
#define BM 128
#define BN 128
#define BKK 16

__global__ void __launch_bounds__(256, 2) sgemm_embed(
    const float* __restrict__ Ft, const float* __restrict__ Fte,
    const float* __restrict__ Wf, const float* __restrict__ bf,
    const float* __restrict__ Wg, const float* __restrict__ bg)
{
    __shared__ ull   As[2][BKK][BM];   // 32 KB (duplicated pairs)
    __shared__ float Bs[2][BKK][BN];   // 16 KB

    const int z   = blockIdx.z;
    const int b   = z >> 1;
    const int mat = z & 1;
    const float* __restrict__ X    = (mat ? Fte : Ft) + (size_t)b * CHW;
    const float* __restrict__ Wm   = mat ? Wg : Wf;
    const float* __restrict__ bias = mat ? bg : bf;
    float* __restrict__ Ob         = (mat ? g_Ee : g_Et) + (size_t)b * CHW;

    const int om = blockIdx.y * BM;
    const int pn = blockIdx.x * BN;

    const int tid = threadIdx.x;
    const int tx = tid & 15, ty = tid >> 4;
    const int o0 = ty * 8,  p0 = tx * 8;

    // A-load mapping: 128 o x 16 k = 512 float4 slots, 2 per thread
    const int aO0 = tid >> 2;              // 0..63
    const int aO1 = aO0 + 64;              // 64..127
    const int aC  = (tid & 3) << 2;        // 0,4,8,12
    // B-load mapping: 16 k x 32 p-quads = 512 float4 slots, 2 per thread
    const int bC  = tid >> 5;              // 0..7
    const int bP  = (tid & 31) << 2;       // 0..124

    ull acc[32];
#pragma unroll
    for (int i = 0; i < 32; i++) acc[i] = 0ULL;

    float4 ra0, ra1, rb0, rb1;

    // prologue: load tile kk=0 and store to buffer 0
    ra0 = *(const float4*)&Wm[(om + aO0)*CH + aC];
    ra1 = *(const float4*)&Wm[(om + aO1)*CH + aC];
    rb0 = *(const float4*)&X[(bC    )*PLANE + pn + bP];
    rb1 = *(const float4*)&X[(bC + 8)*PLANE + pn + bP];
    As[0][aC+0][aO0] = pack2(ra0.x, ra0.x);
    As[0][aC+1][aO0] = pack2(ra0.y, ra0.y);
    As[0][aC+2][aO0] = pack2(ra0.z, ra0.z);
    As[0][aC+3][aO0] = pack2(ra0.w, ra0.w);
    As[0][aC+0][aO1] = pack2(ra1.x, ra1.x);
    As[0][aC+1][aO1] = pack2(ra1.y, ra1.y);
    As[0][aC+2][aO1] = pack2(ra1.z, ra1.z);
    As[0][aC+3][aO1] = pack2(ra1.w, ra1.w);
    *(float4*)&Bs[0][bC    ][bP] = rb0;
    *(float4*)&Bs[0][bC + 8][bP] = rb1;

    const int NT = CH / BKK;   // 16
    for (int t = 0; t < NT; t++) {
        __syncthreads();
        if (t < NT - 1) {
            const int kk = (t + 1) * BKK;
            ra0 = *(const float4*)&Wm[(om + aO0)*CH + kk + aC];
            ra1 = *(const float4*)&Wm[(om + aO1)*CH + kk + aC];
            rb0 = *(const float4*)&X[(kk + bC    )*PLANE + pn + bP];
            rb1 = *(const float4*)&X[(kk + bC + 8)*PLANE + pn + bP];
        }
        const int buf = t & 1;
#pragma unroll
        for (int k = 0; k < BKK; k++) {
            ull a2[8], b2[4];
#pragma unroll
            for (int mo = 0; mo < 8; mo++) a2[mo] = As[buf][k][o0 + mo];
            const ull* bp = (const ull*)&Bs[buf][k][p0];
#pragma unroll
            for (int j = 0; j < 4; j++) b2[j] = bp[j];
#pragma unroll
            for (int mo = 0; mo < 8; mo++) {
#pragma unroll
                for (int j = 0; j < 4; j++)
                    acc[mo*4 + j] = fma2(a2[mo], b2[j], acc[mo*4 + j]);
            }
        }
        if (t < NT - 1) {
            const int nb2 = (t + 1) & 1;
            As[nb2][aC+0][aO0] = pack2(ra0.x, ra0.x);
            As[nb2][aC+1][aO0] = pack2(ra0.y, ra0.y);
            As[nb2][aC+2][aO0] = pack2(ra0.z, ra0.z);
            As[nb2][aC+3][aO0] = pack2(ra0.w, ra0.w);
            As[nb2][aC+0][aO1] = pack2(ra1.x, ra1.x);
            As[nb2][aC+1][aO1] = pack2(ra1.y, ra1.y);
            As[nb2][aC+2][aO1] = pack2(ra1.z, ra1.z);
            As[nb2][aC+3][aO1] = pack2(ra1.w, ra1.w);
            *(float4*)&Bs[nb2][bC    ][bP] = rb0;
            *(float4*)&Bs[nb2][bC + 8][bP] = rb1;
        }
    }

    // epilogue: bias + store
#pragma unroll
    for (int mo = 0; mo < 8; mo++) {
        const int o = om + o0 + mo;
        const float bb = __ldg(&bias[o]);
        float2 v0 = unpack2(acc[mo*4+0]);
        float2 v1 = unpack2(acc[mo*4+1]);
        float2 v2 = unpack2(acc[mo*4+2]);
        float2 v3 = unpack2(acc[mo*4+3]);
        float4 f0 = make_float4(v0.x+bb, v0.y+bb, v1.x+bb, v1.y+bb);
        float4 f1 = make_float4(v2.x+bb, v2.y+bb, v3.x+bb, v3.y+bb);
        *(float4*)&Ob[(size_t)o*PLANE + pn + p0    ] = f0;
        *(float4*)&Ob[(size_t)o*PLANE + pn + p0 + 4] = f1;
    }
}

// =====================================================================
// Kernel 2: fused affinity + softmax + weighted gather
//   Block = 32x8 pixel tile. Phase A: loop 256 channels, accumulate 33
//   affinities per pixel from a zero-padded 40x16 Et halo + Ee tile in
//   double-buffered smem. Phase B: masked softmax in registers.
//   Phase C: loop 256 channels of Ft through the same halo, write NCHW out.
// =====================================================================
#define TW 32
#define TH 8
#define HA 4
#define HWD 40              // TW + 2*HA
#define HHT 16              // TH + 2*HA
#define HSZ (HWD*HHT)       // 640
#define ESZ (TH*TW)         // 256
#define NK 33

__global__ void __launch_bounds__(256) attn_kernel(
    const float* __restrict__ Ft, float* __restrict__ out)
{
    __shared__ float sHalo[2][HSZ];
    __shared__ float sEe[2][ESZ];

    const int b   = blockIdx.z;
    const int ty0 = blockIdx.y * TH;
    const int tx0 = blockIdx.x * TW;
    const int tid = threadIdx.x;
    const int lx = tid & 31, ly = tid >> 5;
    const int gy = ty0 + ly, gx = tx0 + lx;
    const int hy0 = ty0 - HA, hx0 = tx0 - HA;

    const float* __restrict__ Etb = g_Et + (size_t)b * CHW;
    const float* __restrict__ Eeb = g_Ee + (size_t)b * CHW;

    float acc[NK];
#pragma unroll
    for (int k = 0; k < NK; k++) acc[k] = 0.f;

    float rv[4];

    auto loadA = [&](int c){
        const float* Ep = Etb + (size_t)c * PLANE;
        const float* Cp = Eeb + (size_t)c * PLANE;
#pragma unroll
        for (int j = 0; j < 4; j++) {
            const int i = tid + j*256;
            float v = 0.f;
            if (i < HSZ) {
                const int yy = i / HWD, xx = i - yy*HWD;
                const int py = hy0 + yy, px = hx0 + xx;
                if ((unsigned)py < HDIM && (unsigned)px < HDIM)
                    v = Ep[py*HDIM + px];
            } else {
                const int e = i - HSZ;
                if (e < ESZ) {
                    const int yy = e >> 5, xx = e & 31;
                    v = Cp[(ty0 + yy)*HDIM + tx0 + xx];
                }
            }
            rv[j] = v;
        }
    };
    auto storeA = [&](int buf){
#pragma unroll
        for (int j = 0; j < 4; j++) {
            const int i = tid + j*256;
            if (i < HSZ) sHalo[buf][i] = rv[j];
            else if (i - HSZ < ESZ) sEe[buf][i - HSZ] = rv[j];
        }
    };

    // ---------------- Phase A: affinity accumulation ----------------
    loadA(0);
    storeA(0);
    loadA(1);
    for (int c = 0; c < CH; c++) {
        __syncthreads();
        if (c + 1 < CH) storeA((c + 1) & 1);
        if (c + 2 < CH) loadA(c + 2);
        const int buf = c & 1;
        const float ee = sEe[buf][ly*TW + lx];
        const float* hp = &sHalo[buf][(ly + HA)*HWD + (lx + HA)];
        acc[0] += ee * hp[0];
#pragma unroll
        for (int s = 1; s <= 4; s++) {
#pragma unroll
            for (int a = -1; a <= 1; a++) {
#pragma unroll
                for (int d = -1; d <= 1; d++) {
                    if (a == 0 && d == 0) continue;
                    const int tt  = (a + 1)*3 + (d + 1);
                    const int idx = 1 + (s - 1)*8 + (tt < 4 ? tt : tt - 1);
                    acc[idx] += ee * hp[a*s*HWD + d*s];
                }
            }
        }
    }

    // ---------------- Phase B: masked softmax (registers) ----------------
#pragma unroll
    for (int s = 1; s <= 4; s++) {
#pragma unroll
        for (int a = -1; a <= 1; a++) {
#pragma unroll
            for (int d = -1; d <= 1; d++) {
                if (a == 0 && d == 0) continue;
                const int tt  = (a + 1)*3 + (d + 1);
                const int idx = 1 + (s - 1)*8 + (tt < 4 ? tt : tt - 1);
                const int py = gy + a*s, px = gx + d*s;
                if (!((unsigned)py < HDIM && (unsigned)px < HDIM))
                    acc[idx] = -1e30f;
            }
        }
    }
    float m = acc[0];
#pragma unroll
    for (int k = 1; k < NK; k++) m = fmaxf(m, acc[k]);
    float ssum = 0.f;
#pragma unroll
    for (int k = 0; k < NK; k++) { acc[k] = __expf(acc[k] - m); ssum += acc[k]; }
    const float inv = 1.f / ssum;
#pragma unroll
    for (int k = 0; k < NK; k++) acc[k] *= inv;

    // ---------------- Phase C: weighted gather of Ft ----------------
    const float* __restrict__ Fb   = Ft  + (size_t)b * CHW;
    float* __restrict__       Outb = out + (size_t)b * CHW;

    auto loadC = [&](int c){
        const float* Fp = Fb + (size_t)c * PLANE;
#pragma unroll
        for (int j = 0; j < 3; j++) {
            const int i = tid + j*256;
            float v = 0.f;
            if (i < HSZ) {
                const int yy = i / HWD, xx = i - yy*HWD;
                const int py = hy0 + yy, px = hx0 + xx;
                if ((unsigned)py < HDIM && (unsigned)px < HDIM)
                    v = Fp[py*HDIM + px];
            }
            rv[j] = v;
        }
    };
    auto storeC = [&](int buf){
#pragma unroll
        for (int j = 0; j < 3; j++) {
            const int i = tid + j*256;
            if (i < HSZ) sHalo[buf][i] = rv[j];
        }
    };

    loadC(0);
    storeC(0);   // safe: buffer 0 last read at c=254, completed before barrier c=255
    loadC(1);
    const int obase = gy*HDIM + gx;
    for (int c = 0; c < CH; c++) {
        __syncthreads();
        if (c + 1 < CH) storeC((c + 1) & 1);
        if (c + 2 < CH) loadC(c + 2);
        const int buf = c & 1;
        const float* hp = &sHalo[buf][(ly + HA)*HWD + (lx + HA)];
        float o = acc[0] * hp[0];
#pragma unroll
        for (int s = 1; s <= 4; s++) {
#pragma unroll
            for (int a = -1; a <= 1; a++) {
#pragma unroll
                for (int d = -1; d <= 1; d++) {
                    if (a == 0 && d == 0) continue;
                    const int tt  = (a + 1)*3 + (d + 1);
                    const int idx = 1 + (s - 1)*8 + (tt < 4 ? tt : tt - 1);
                    o += acc[idx] * hp[a*s*HWD + d*s];
                }
            }
        }
        Outb[(size_t)c*PLANE + obase] = o;
    }
}

// =====================================================================
extern "C" void kernel_launch(void* const* d_in, const int* in_sizes, int n_in,
                              void* d_out, int out_size)
{
    const float* Ft  = (const float*)d_in[0];
    const float* Fte = (const float*)d_in[1];
    const float* Wf  = (const float*)d_in[2];
    const float* bf  = (const float*)d_in[3];
    const float* Wg  = (const float*)d_in[4];
    const float* bg  = (const float*)d_in[5];
    float* out = (float*)d_out;

    dim3 g1(PLANE / BN, CH / BM, NB * 2);   // (72, 2, 8)
    sgemm_embed<<<g1, 256>>>(Ft, Fte, Wf, bf, Wg, bg);

    dim3 g2(HDIM / TW, HDIM / TH, NB);      // (3, 12, 4)
    attn_kernel<<<g2, 256>>>(Ft, out);
}

// round 3
// speedup vs baseline: 1.6690x; 1.6690x over previous
#include <cuda_runtime.h>

// ---------------- problem constants ----------------
#define HDIM 96
#define CH   256
#define NB   4
#define PLANE (HDIM*HDIM)       // 9216
#define CHW   (CH*PLANE)        // 2359296
#define NK 33

// scratch
__device__ float g_Et[NB*CHW];
__device__ float g_Ee[NB*CHW];
#define CSPLIT 4
#define CPC (CH/CSPLIT)         // 64 channels per chunk
__device__ float g_Ap[CSPLIT*NB*NK*PLANE];   // affinity partials
__device__ float g_Wt[NB*NK*PLANE];          // softmax weights

// ---------------- helpers ----------------
typedef unsigned long long ull;
__device__ __forceinline__ ull pack2(float x, float y){
    ull r; asm("mov.b64 %0, {%1,%2};" : "=l"(r) : "f"(x), "f"(y)); return r;
}
__device__ __forceinline__ ull fma2(ull a, ull b, ull c){
    ull r; asm("fma.rn.f32x2 %0, %1, %2, %3;" : "=l"(r) : "l"(a), "l"(b), "l"(c)); return r;
}
__device__ __forceinline__ float2 unpack2(ull v){
    float2 f; asm("mov.b64 {%0,%1}, %2;" : "=f"(f.x), "=f"(f.y) : "l"(v)); return f;
}
__device__ __forceinline__ unsigned smaddr(const void* p){
    return (unsigned)__cvta_generic_to_shared(p);
}
__device__ __forceinline__ void cpa16(unsigned dst, const void* src){
    asm volatile("cp.async.ca.shared.global [%0], [%1], 16;" :: "r"(dst), "l"(src));
}
__device__ __forceinline__ void cpa4(unsigned dst, const void* src, int srcbytes){
    asm volatile("cp.async.ca.shared.global [%0], [%1], 4, %2;"
                 :: "r"(dst), "l"(src), "r"(srcbytes));
}
#define CP_COMMIT() asm volatile("cp.async.commit_group;")
#define CP_WAIT(N)  asm volatile("cp.async.wait_group %0;" :: "n"(N))

// tap index mapping (consistent across kernels; softmax is order-invariant)
__device__ __forceinline__ int tap_idx(int s, int a, int d){
    const int tt = (a + 1)*3 + (d + 1);
    return 1 + (s - 1)*8 + (tt < 4 ? tt : tt - 1);
}

// =====================================================================
// Kernel 1: fused dual SGEMM (1x1 conv embeddings), f32x2 FMA core.
// B tile via cp.async (latency covered by full-tile compute).
// =====================================================================
#define BM 128
#define BN 128
#define BKK 16

__global__ void __launch_bounds__(256, 2) sgemm_embed(
    const float* __restrict__ Ft, const float* __restrict__ Fte,
    const float* __restrict__ Wf, const float* __restrict__ bf,
    const float* __restrict__ Wg, const float* __restrict__ bg)
{
    __shared__ __align__(16) ull   As[2][BKK][BM];   // 32 KB (dup pairs)
    __shared__ __align__(16) float Bs[2][BKK][BN];   // 16 KB

    const int z   = blockIdx.z;
    const int b   = z >> 1;
    const int mat = z & 1;
    const float* __restrict__ X    = (mat ? Fte : Ft) + (size_t)b * CHW;
    const float* __restrict__ Wm   = mat ? Wg : Wf;
    const float* __restrict__ bias = mat ? bg : bf;
    float* __restrict__ Ob         = (mat ? g_Ee : g_Et) + (size_t)b * CHW;

    const int om = blockIdx.y * BM;
    const int pn = blockIdx.x * BN;

    const int tid = threadIdx.x;
    const int tx = tid & 15, ty = tid >> 4;
    const int o0 = ty * 8,  p0 = tx * 8;

    const int aO0 = tid >> 2;
    const int aO1 = aO0 + 64;
    const int aC  = (tid & 3) << 2;
    const int bC  = tid >> 5;
    const int bP  = (tid & 31) << 2;

    ull acc[32];
#pragma unroll
    for (int i = 0; i < 32; i++) acc[i] = 0ULL;

    float4 ra0, ra1;

    // prologue: B tile 0 via cp.async, A tile 0 via registers
    cpa16(smaddr(&Bs[0][bC    ][bP]), &X[(bC    )*PLANE + pn + bP]);
    cpa16(smaddr(&Bs[0][bC + 8][bP]), &X[(bC + 8)*PLANE + pn + bP]);
    CP_COMMIT();
    ra0 = *(const float4*)&Wm[(om + aO0)*CH + aC];
    ra1 = *(const float4*)&Wm[(om + aO1)*CH + aC];
    As[0][aC+0][aO0] = pack2(ra0.x, ra0.x);
    As[0][aC+1][aO0] = pack2(ra0.y, ra0.y);
    As[0][aC+2][aO0] = pack2(ra0.z, ra0.z);
    As[0][aC+3][aO0] = pack2(ra0.w, ra0.w);
    As[0][aC+0][aO1] = pack2(ra1.x, ra1.x);
    As[0][aC+1][aO1] = pack2(ra1.y, ra1.y);
    As[0][aC+2][aO1] = pack2(ra1.z, ra1.z);
    As[0][aC+3][aO1] = pack2(ra1.w, ra1.w);
    CP_WAIT(0);
    __syncthreads();

    const int NT = CH / BKK;   // 16
    for (int t = 0; t < NT; t++) {
        if (t < NT - 1) {
            const int kk = (t + 1) * BKK;
            const int nb2 = (t + 1) & 1;
            cpa16(smaddr(&Bs[nb2][bC    ][bP]), &X[(kk + bC    )*PLANE + pn + bP]);
            cpa16(smaddr(&Bs[nb2][bC + 8][bP]), &X[(kk + bC + 8)*PLANE + pn + bP]);
            CP_COMMIT();
            ra0 = *(const float4*)&Wm[(om + aO0)*CH + kk + aC];
            ra1 = *(const float4*)&Wm[(om + aO1)*CH + kk + aC];
        }
        const int buf = t & 1;
#pragma unroll
        for (int k = 0; k < BKK; k++) {
            ull a2[8], b2[4];
#pragma unroll
            for (int mo = 0; mo < 8; mo++) a2[mo] = As[buf][k][o0 + mo];
            const ull* bp = (const ull*)&Bs[buf][k][p0];
#pragma unroll
            for (int j = 0; j < 4; j++) b2[j] = bp[j];
#pragma unroll
            for (int mo = 0; mo < 8; mo++) {
#pragma unroll
                for (int j = 0; j < 4; j++)
                    acc[mo*4 + j] = fma2(a2[mo], b2[j], acc[mo*4 + j]);
            }
        }
        if (t < NT - 1) {
            const int nb2 = (t + 1) & 1;
            As[nb2][aC+0][aO0] = pack2(ra0.x, ra0.x);
            As[nb2][aC+1][aO0] = pack2(ra0.y, ra0.y);
            As[nb2][aC+2][aO0] = pack2(ra0.z, ra0.z);
            As[nb2][aC+3][aO0] = pack2(ra0.w, ra0.w);
            As[nb2][aC+0][aO1] = pack2(ra1.x, ra1.x);
            As[nb2][aC+1][aO1] = pack2(ra1.y, ra1.y);
            As[nb2][aC+2][aO1] = pack2(ra1.z, ra1.z);
            As[nb2][aC+3][aO1] = pack2(ra1.w, ra1.w);
            CP_WAIT(0);
            __syncthreads();
        }
    }

#pragma unroll
    for (int mo = 0; mo < 8; mo++) {
        const int o = om + o0 + mo;
        const float bb = __ldg(&bias[o]);
        float2 v0 = unpack2(acc[mo*4+0]);
        float2 v1 = unpack2(acc[mo*4+1]);
        float2 v2 = unpack2(acc[mo*4+2]);
        float2 v3 = unpack2(acc[mo*4+3]);
        float4 f0 = make_float4(v0.x+bb, v0.y+bb, v1.x+bb, v1.y+bb);
        float4 f1 = make_float4(v2.x+bb, v2.y+bb, v3.x+bb, v3.y+bb);
        *(float4*)&Ob[(size_t)o*PLANE + pn + p0    ] = f0;
        *(float4*)&Ob[(size_t)o*PLANE + pn + p0 + 4] = f1;
    }
}

// =====================================================================
// Attention constants: 32x8 pixel tile, 4-dilation halo
// =====================================================================
#define TW 32
#define TH 8
#define HA 4
#define HWD 40              // TW + 2*HA
#define HHT 16              // TH + 2*HA
#define HSZ (HWD*HHT)       // 640
#define ESZ (TH*TW)         // 256
#define STG_A (HSZ+ESZ)     // 896: halo [0,640) + Ee [640,896)
#define NSTAGE 4

// =====================================================================
// Kernel 2a: affinity partials. grid (3,12,NB*CSPLIT)=576 blocks.
// Each block: one 32x8 tile, one 64-channel chunk, cp.async 4-stage.
// =====================================================================
__global__ void __launch_bounds__(256) affinity_kernel()
{
    __shared__ float st[NSTAGE][STG_A];

    const int z     = blockIdx.z;
    const int b     = z & (NB - 1);
    const int chunk = z >> 2;
    const int c0    = chunk * CPC;

    const int ty0 = blockIdx.y * TH;
    const int tx0 = blockIdx.x * TW;
    const int tid = threadIdx.x;
    const int lx = tid & 31, ly = tid >> 5;
    const int gy = ty0 + ly, gx = tx0 + lx;
    const int hy0 = ty0 - HA, hx0 = tx0 - HA;

    const float* __restrict__ Etb = g_Et + (size_t)b * CHW;
    const float* __restrict__ Eeb = g_Ee + (size_t)b * CHW;

    // precompute per-thread copy slots (channel-independent)
    int  srcOff[4], vb[4];
    bool isEe[4];
#pragma unroll
    for (int j = 0; j < 4; j++) {
        const int i = tid + j*256;
        if (i < HSZ) {
            const int yy = i / HWD, xx = i - yy*HWD;
            const int py = hy0 + yy, px = hx0 + xx;
            const bool valid = ((unsigned)py < HDIM) && ((unsigned)px < HDIM);
            const int pyc = min(max(py, 0), HDIM-1);
            const int pxc = min(max(px, 0), HDIM-1);
            srcOff[j] = pyc*HDIM + pxc;
            vb[j] = valid ? 4 : 0;
            isEe[j] = false;
        } else if (i < STG_A) {
            const int e = i - HSZ;
            const int yy = e >> 5, xx = e & 31;
            srcOff[j] = (ty0 + yy)*HDIM + tx0 + xx;
            vb[j] = 4;
            isEe[j] = true;
        } else {
            vb[j] = -1;
        }
    }

    auto issue = [&](int c, int s){
#pragma unroll
        for (int j = 0; j < 4; j++) {
            if (vb[j] >= 0) {
                const float* src = (isEe[j] ? Eeb : Etb) + (size_t)c*PLANE + srcOff[j];
                cpa4(smaddr(&st[s][tid + j*256]), src, vb[j]);
            }
        }
        CP_COMMIT();
    };

    float acc[NK];
#pragma unroll
    for (int k = 0; k < NK; k++) acc[k] = 0.f;

    issue(c0 + 0, 0);
    issue(c0 + 1, 1);
    issue(c0 + 2, 2);

    for (int c = 0; c < CPC; c++) {
        CP_WAIT(2);            // stage c complete
        __syncthreads();       // all copies + prior readers done
        if (c + 3 < CPC) issue(c0 + c + 3, (c + 3) & (NSTAGE-1));
        else CP_COMMIT();      // keep group count uniform

        const int buf = c & (NSTAGE-1);
        const float ee = st[buf][HSZ + ly*TW + lx];
        const float* hp = &st[buf][(ly + HA)*HWD + (lx + HA)];
        acc[0] += ee * hp[0];
#pragma unroll
        for (int s = 1; s <= 4; s++) {
#pragma unroll
            for (int a = -1; a <= 1; a++) {
#pragma unroll
                for (int d = -1; d <= 1; d++) {
                    if (a == 0 && d == 0) continue;
                    acc[tap_idx(s,a,d)] += ee * hp[a*s*HWD + d*s];
                }
            }
        }
    }

    // write partials: g_Ap[chunk][b][k][p]
    const size_t base = ((size_t)(chunk*NB + b)*NK)*PLANE + gy*HDIM + gx;
#pragma unroll
    for (int k = 0; k < NK; k++)
        g_Ap[base + (size_t)k*PLANE] = acc[k];
}

// =====================================================================
// Kernel 2b: combine partials + masked softmax -> weights g_Wt[b][k][p]
// grid 144 x 256 threads, 1 pixel/thread.
// =====================================================================
__global__ void __launch_bounds__(256) softmax_kernel()
{
    const int g = blockIdx.x*256 + threadIdx.x;   // over NB*PLANE
    const int b = g / PLANE;
    const int p = g - b*PLANE;
    const int py = p / HDIM, px = p - py*HDIM;

    float a[NK];
#pragma unroll
    for (int k = 0; k < NK; k++) a[k] = 0.f;
#pragma unroll
    for (int ch = 0; ch < CSPLIT; ch++) {
        const size_t base = ((size_t)(ch*NB + b)*NK)*PLANE + p;
#pragma unroll
        for (int k = 0; k < NK; k++)
            a[k] += g_Ap[base + (size_t)k*PLANE];
    }

    // mask invalid taps
#pragma unroll
    for (int s = 1; s <= 4; s++) {
#pragma unroll
        for (int aa = -1; aa <= 1; aa++) {
#pragma unroll
            for (int d = -1; d <= 1; d++) {
                if (aa == 0 && d == 0) continue;
                const int yy = py + aa*s, xx = px + d*s;
                if (!(((unsigned)yy < HDIM) && ((unsigned)xx < HDIM)))
                    a[tap_idx(s,aa,d)] = -1e30f;
            }
        }
    }
    float m = a[0];
#pragma unroll
    for (int k = 1; k < NK; k++) m = fmaxf(m, a[k]);
    float ssum = 0.f;
#pragma unroll
    for (int k = 0; k < NK; k++) { a[k] = __expf(a[k] - m); ssum += a[k]; }
    const float inv = 1.f / ssum;

    const size_t wbase = ((size_t)b*NK)*PLANE + p;
#pragma unroll
    for (int k = 0; k < NK; k++)
        g_Wt[wbase + (size_t)k*PLANE] = a[k] * inv;
}

// =====================================================================
// Kernel 2c: weighted gather. grid (3,12,NB*CSPLIT)=576 blocks.
// Each block: one tile, 64 output channels, cp.async 4-stage halo.
// =====================================================================
__global__ void __launch_bounds__(256) gather_kernel(
    const float* __restrict__ Ft, float* __restrict__ out)
{
    __shared__ float st[NSTAGE][HSZ];

    const int z     = blockIdx.z;
    const int b     = z & (NB - 1);
    const int chunk = z >> 2;
    const int c0    = chunk * CPC;

    const int ty0 = blockIdx.y * TH;
    const int tx0 = blockIdx.x * TW;
    const int tid = threadIdx.x;
    const int lx = tid & 31, ly = tid >> 5;
    const int gy = ty0 + ly, gx = tx0 + lx;
    const int hy0 = ty0 - HA, hx0 = tx0 - HA;

    const float* __restrict__ Fb = Ft + (size_t)b * CHW;
    float* __restrict__ Outb     = out + (size_t)b * CHW;

    // load weights for this pixel
    float w[NK];
    {
        const size_t wbase = ((size_t)b*NK)*PLANE + gy*HDIM + gx;
#pragma unroll
        for (int k = 0; k < NK; k++)
            w[k] = __ldg(&g_Wt[wbase + (size_t)k*PLANE]);
    }

    int srcOff[3], vb[3];
#pragma unroll
    for (int j = 0; j < 3; j++) {
        const int i = tid + j*256;
        if (i < HSZ) {
            const int yy = i / HWD, xx = i - yy*HWD;
            const int py = hy0 + yy, px = hx0 + xx;
            const bool valid = ((unsigned)py < HDIM) && ((unsigned)px < HDIM);
            const int pyc = min(max(py, 0), HDIM-1);
            const int pxc = min(max(px, 0), HDIM-1);
            srcOff[j] = pyc*HDIM + pxc;
            vb[j] = valid ? 4 : 0;
        } else vb[j] = -1;
    }

    auto issue = [&](int c, int s){
#pragma unroll
        for (int j = 0; j < 3; j++) {
            if (vb[j] >= 0)
                cpa4(smaddr(&st[s][tid + j*256]), Fb + (size_t)c*PLANE + srcOff[j], vb[j]);
        }
        CP_COMMIT();
    };

    issue(c0 + 0, 0);
    issue(c0 + 1, 1);
    issue(c0 + 2, 2);

    const int obase = gy*HDIM + gx;
    for (int c = 0; c < CPC; c++) {
        CP_WAIT(2);
        __syncthreads();
        if (c + 3 < CPC) issue(c0 + c + 3, (c + 3) & (NSTAGE-1));
        else CP_COMMIT();

        const int buf = c & (NSTAGE-1);
        const float* hp = &st[buf][(ly + HA)*HWD + (lx + HA)];
        float o = w[0] * hp[0];
#pragma unroll
        for (int s = 1; s <= 4; s++) {
#pragma unroll
            for (int a = -1; a <= 1; a++) {
#pragma unroll
                for (int d = -1; d <= 1; d++) {
                    if (a == 0 && d == 0) continue;
                    o += w[tap_idx(s,a,d)] * hp[a*s*HWD + d*s];
                }
            }
        }
        Outb[(size_t)(c0 + c)*PLANE + obase] = o;
    }
}

// =====================================================================
extern "C" void kernel_launch(void* const* d_in, const int* in_sizes, int n_in,
                              void* d_out, int out_size)
{
    const float* Ft  = (const float*)d_in[0];
    const float* Fte = (const float*)d_in[1];
    const float* Wf  = (const float*)d_in[2];
    const float* bf  = (const float*)d_in[3];
    const float* Wg  = (const float*)d_in[4];
    const float* bg  = (const float*)d_in[5];
    float* out = (float*)d_out;

    dim3 g1(PLANE / BN, CH / BM, NB * 2);     // (72, 2, 8)
    sgemm_embed<<<g1, 256>>>(Ft, Fte, Wf, bf, Wg, bg);

    dim3 g2(HDIM / TW, HDIM / TH, NB * CSPLIT);  // (3, 12, 16) = 576
    affinity_kernel<<<g2, 256>>>();

    softmax_kernel<<<NB*PLANE/256, 256>>>();     // 144 blocks

    gather_kernel<<<g2, 256>>>(Ft, out);
}

// round 7
// speedup vs baseline: 2.3474x; 1.4065x over previous
#include <cuda_runtime.h>
#include <cuda_bf16.h>
#include <cstdint>

// ---------------- problem constants ----------------
#define HDIM 96
#define CH   256
#define NB   4
#define PLANE (HDIM*HDIM)       // 9216
#define CHW   (CH*PLANE)        // 2359296
#define NK 33

// scratch
__device__ float g_Et[NB*CHW];
__device__ float g_Ee[NB*CHW];
#define CSPLIT 4
#define CPC (CH/CSPLIT)         // 64
__device__ float g_Ap[CSPLIT*NB*NK*PLANE];
__device__ float g_Wt[NB*NK*PLANE];
// 2-term bf16 split: Xs[(in*2+term)*NB+b][p][c], Ws[(mat*2+term)][o][c]
__device__ __nv_bfloat16 g_Xs[2*2*NB*(size_t)PLANE*CH];   // 75.5 MB
__device__ __nv_bfloat16 g_Ws[2*2*CH*CH];

// ---------------- helpers ----------------
__device__ __forceinline__ unsigned smaddr(const void* p){
    return (unsigned)__cvta_generic_to_shared(p);
}
__device__ __forceinline__ void cpa4(unsigned dst, const void* src, int srcbytes){
    asm volatile("cp.async.ca.shared.global [%0], [%1], 4, %2;"
                 :: "r"(dst), "l"(src), "r"(srcbytes));
}
__device__ __forceinline__ void cpa16(unsigned dst, const void* src){
    asm volatile("cp.async.ca.shared.global [%0], [%1], 16;" :: "r"(dst), "l"(src));
}
#define CP_COMMIT() asm volatile("cp.async.commit_group;")
#define CP_WAIT(N)  asm volatile("cp.async.wait_group %0;" :: "n"(N))

__device__ __forceinline__ int tap_idx(int s, int a, int d){
    const int tt = (a + 1)*3 + (d + 1);
    return 1 + (s - 1)*8 + (tt < 4 ? tt : tt - 1);
}

__device__ __forceinline__ void ldsm4(uint32_t* r, unsigned addr){
    asm volatile("ldmatrix.sync.aligned.m8n8.x4.shared.b16 {%0,%1,%2,%3}, [%4];"
        : "=r"(r[0]), "=r"(r[1]), "=r"(r[2]), "=r"(r[3]) : "r"(addr));
}
__device__ __forceinline__ void mma16816(float* d, const uint32_t* a, const uint32_t* b){
    asm volatile(
        "mma.sync.aligned.m16n8k16.row.col.f32.bf16.bf16.f32 "
        "{%0,%1,%2,%3}, {%4,%5,%6,%7}, {%8,%9}, {%0,%1,%2,%3};"
        : "+f"(d[0]), "+f"(d[1]), "+f"(d[2]), "+f"(d[3])
        : "r"(a[0]), "r"(a[1]), "r"(a[2]), "r"(a[3]), "r"(b[0]), "r"(b[1]));
}

// =====================================================================
// Kernel 0a: split W (fp32 -> 2 x bf16) : g_Ws[(mat*2+term)][o][c]
// =====================================================================
__global__ void __launch_bounds__(256) split_w(
    const float* __restrict__ Wf, const float* __restrict__ Wg)
{
    const int idx = blockIdx.x*256 + threadIdx.x;   // over 2*65536
    const int mat = idx >> 16;
    const int e   = idx & 65535;
    const float x = (mat ? Wg : Wf)[e];
    __nv_bfloat16 b1 = __float2bfloat16(x);
    __nv_bfloat16 b2 = __float2bfloat16(x - __bfloat162float(b1));
    g_Ws[(size_t)(mat*2 + 0)*65536 + e] = b1;
    g_Ws[(size_t)(mat*2 + 1)*65536 + e] = b2;
}

// =====================================================================
// Kernel 0b: split + transpose X: [c][p] fp32 -> [p][c] bf16 x2 terms
// grid (288, 8, 8=input*b), 256 thr, 32x32 tiles
// =====================================================================
__global__ void __launch_bounds__(256) split_x(
    const float* __restrict__ Ft, const float* __restrict__ Fte)
{
    __shared__ __nv_bfloat16 t[2][32][34];
    const int z  = blockIdx.z;
    const int in = z >> 2, b = z & 3;
    const float* __restrict__ src = (in ? Fte : Ft) + (size_t)b * CHW;
    const int c0 = blockIdx.y*32, p0 = blockIdx.x*32;
    const int tx = threadIdx.x & 31, ty = threadIdx.x >> 5;

#pragma unroll
    for (int i = 0; i < 4; i++) {
        const int cl = ty + i*8;
        const float x = src[(size_t)(c0 + cl)*PLANE + p0 + tx];
        __nv_bfloat16 b1 = __float2bfloat16(x);
        __nv_bfloat16 b2 = __float2bfloat16(x - __bfloat162float(b1));
        t[0][cl][tx] = b1; t[1][cl][tx] = b2;
    }
    __syncthreads();
#pragma unroll
    for (int i = 0; i < 4; i++) {
        const int pl = ty + i*8;
        const size_t po = (size_t)(p0 + pl)*CH + c0 + tx;
        // g_XsT[p][c] = X[c][p]:  value at (p0+pl, c0+tx) is t[term][tx][pl]
#pragma unroll
        for (int term = 0; term < 2; term++) {
            g_Xs[((size_t)((in*2 + term)*NB + b))*((size_t)PLANE*CH) + po] = t[term][tx][pl];
        }
    }
}

// =====================================================================
// Kernel 1: bf16 mma.sync GEMM with 2-term split stacked as K=768.
//   Out[o][p] = sum_k A'[o][k] B'[k][p],  A'=[W1|W1|W2], B'=[X1;X2;X1]
//   Tile 128x128xK32, 8 warps (2M x 4N), warp tile 64x32, m16n8k16.
//   TN layout: A [o][k] k-contig, B [p][k] k-contig; padded 40-elem rows.
// grid (72, 2, 8=b*mat), 256 threads.
// =====================================================================
#define GROW 40          // padded row length (bf16): 32 data + 8 pad
#define GITERS 24        // 768 / 32

__global__ void __launch_bounds__(256, 2) gemm_mma(
    const float* __restrict__ bfv, const float* __restrict__ bgv)
{
    __shared__ __align__(16) __nv_bfloat16 sA[2][128*GROW];   // 10 KB each
    __shared__ __align__(16) __nv_bfloat16 sB[2][128*GROW];

    const int tid  = threadIdx.x;
    const int lane = tid & 31;
    const int wid  = tid >> 5;
    const int wm   = wid >> 2;          // 0..1  (M)
    const int wn   = wid & 3;           // 0..3  (N)
    const int z    = blockIdx.z;
    const int b    = z & 3, mat = z >> 2;
    const int om   = blockIdx.y * 128;
    const int pn   = blockIdx.x * 128;

    const float* __restrict__ bias = mat ? bgv : bfv;
    float* __restrict__ Ob = (mat ? g_Ee : g_Et) + (size_t)b * CHW;

    const int At[3] = {0, 0, 1};
    const int Ct[3] = {0, 1, 0};

    // cp.async mapping: 512 16B-chunks per operand, 2 per thread each
    auto issueTile = [&](int t){
        const int st   = t & 1;
        const int kseg = t >> 3;              // 0..2
        const int kin  = (t & 7) * 32;        // k offset within 256-segment
        const __nv_bfloat16* __restrict__ Wb =
            g_Ws + (size_t)(mat*2 + At[kseg])*65536;
        const __nv_bfloat16* __restrict__ Xb =
            g_Xs + ((size_t)((mat*2 + Ct[kseg])*NB + b))*((size_t)PLANE*CH);
#pragma unroll
        for (int j = 0; j < 2; j++) {
            const int idx = tid + j*256;
            const int row = idx >> 2, ch = idx & 3;
            cpa16(smaddr(&sA[st][row*GROW + ch*8]),
                  Wb + (size_t)(om + row)*CH + kin + ch*8);
        }
#pragma unroll
        for (int j = 0; j < 2; j++) {
            const int idx = tid + j*256;
            const int row = idx >> 2, ch = idx & 3;
            cpa16(smaddr(&sB[st][row*GROW + ch*8]),
                  Xb + (size_t)(pn + row)*CH + kin + ch*8);
        }
        CP_COMMIT();
    };

    float acc[4][4][4];
#pragma unroll
    for (int i = 0; i < 4; i++)
#pragma unroll
        for (int j = 0; j < 4; j++)
#pragma unroll
            for (int e = 0; e < 4; e++) acc[i][j][e] = 0.f;

    issueTile(0);

    for (int t = 0; t < GITERS; t++) {
        if (t < GITERS - 1) { issueTile(t + 1); CP_WAIT(1); }
        else                { CP_WAIT(0); }
        __syncthreads();

        const int st = t & 1;
        const unsigned aBase = smaddr(&sA[st][0]);
        const unsigned bBase = smaddr(&sB[st][0]);
#pragma unroll
        for (int ks = 0; ks < 2; ks++) {
            const int kb = ks * 32;   // byte offset of k16 step
            uint32_t a[4][4];
#pragma unroll
            for (int i = 0; i < 4; i++) {
                const int row = wm*64 + i*16 + (lane & 15);
                ldsm4(a[i], aBase + row*(GROW*2) + kb + ((lane >> 4)*16));
            }
            uint32_t bf[4][2];
#pragma unroll
            for (int j = 0; j < 2; j++) {
                const int g = lane >> 3;
                const int nrow = wn*32 + j*16 + ((g >> 1)*8) + (lane & 7);
                uint32_t r[4];
                ldsm4(r, bBase + nrow*(GROW*2) + kb + ((g & 1)*16));
                bf[2*j][0]   = r[0]; bf[2*j][1]   = r[1];
                bf[2*j+1][0] = r[2]; bf[2*j+1][1] = r[3];
            }
#pragma unroll
            for (int i = 0; i < 4; i++)
#pragma unroll
                for (int j = 0; j < 4; j++)
                    mma16816(acc[i][j], a[i], bf[j]);
        }
        __syncthreads();
    }

    // epilogue: bias + store fp32
#pragma unroll
    for (int i = 0; i < 4; i++) {
        const int o0 = om + wm*64 + i*16 + (lane >> 2);
        const float bb0 = __ldg(&bias[o0]);
        const float bb1 = __ldg(&bias[o0 + 8]);
#pragma unroll
        for (int j = 0; j < 4; j++) {
            const int p = pn + wn*32 + j*8 + (lane & 3)*2;
            float2 v0 = make_float2(acc[i][j][0] + bb0, acc[i][j][1] + bb0);
            float2 v1 = make_float2(acc[i][j][2] + bb1, acc[i][j][3] + bb1);
            *(float2*)&Ob[(size_t)o0*PLANE + p]       = v0;
            *(float2*)&Ob[(size_t)(o0+8)*PLANE + p]   = v1;
        }
    }
}

// =====================================================================
// Attention (unchanged from round 3: passing, ~162us combined)
// =====================================================================
#define TW 32
#define TH 8
#define HA 4
#define HWD 40
#define HHT 16
#define HSZ (HWD*HHT)       // 640
#define ESZ (TH*TW)         // 256
#define STG_A (HSZ+ESZ)     // 896
#define NSTAGE 4

__global__ void __launch_bounds__(256) affinity_kernel()
{
    __shared__ float st[NSTAGE][STG_A];

    const int z     = blockIdx.z;
    const int b     = z & (NB - 1);
    const int chunk = z >> 2;
    const int c0    = chunk * CPC;

    const int ty0 = blockIdx.y * TH;
    const int tx0 = blockIdx.x * TW;
    const int tid = threadIdx.x;
    const int lx = tid & 31, ly = tid >> 5;
    const int gy = ty0 + ly, gx = tx0 + lx;
    const int hy0 = ty0 - HA, hx0 = tx0 - HA;

    const float* __restrict__ Etb = g_Et + (size_t)b * CHW;
    const float* __restrict__ Eeb = g_Ee + (size_t)b * CHW;

    int  srcOff[4], vb[4];
    bool isEe[4];
#pragma unroll
    for (int j = 0; j < 4; j++) {
        const int i = tid + j*256;
        if (i < HSZ) {
            const int yy = i / HWD, xx = i - yy*HWD;
            const int py = hy0 + yy, px = hx0 + xx;
            const bool valid = ((unsigned)py < HDIM) && ((unsigned)px < HDIM);
            const int pyc = min(max(py, 0), HDIM-1);
            const int pxc = min(max(px, 0), HDIM-1);
            srcOff[j] = pyc*HDIM + pxc;
            vb[j] = valid ? 4 : 0;
            isEe[j] = false;
        } else if (i < STG_A) {
            const int e = i - HSZ;
            const int yy = e >> 5, xx = e & 31;
            srcOff[j] = (ty0 + yy)*HDIM + tx0 + xx;
            vb[j] = 4;
            isEe[j] = true;
        } else {
            vb[j] = -1;
        }
    }

    auto issue = [&](int c, int s){
#pragma unroll
        for (int j = 0; j < 4; j++) {
            if (vb[j] >= 0) {
                const float* src = (isEe[j] ? Eeb : Etb) + (size_t)c*PLANE + srcOff[j];
                cpa4(smaddr(&st[s][tid + j*256]), src, vb[j]);
            }
        }
        CP_COMMIT();
    };

    float acc[NK];
#pragma unroll
    for (int k = 0; k < NK; k++) acc[k] = 0.f;

    issue(c0 + 0, 0);
    issue(c0 + 1, 1);
    issue(c0 + 2, 2);

    for (int c = 0; c < CPC; c++) {
        CP_WAIT(2);
        __syncthreads();
        if (c + 3 < CPC) issue(c0 + c + 3, (c + 3) & (NSTAGE-1));
        else CP_COMMIT();

        const int buf = c & (NSTAGE-1);
        const float ee = st[buf][HSZ + ly*TW + lx];
        const float* hp = &st[buf][(ly + HA)*HWD + (lx + HA)];
        acc[0] += ee * hp[0];
#pragma unroll
        for (int s = 1; s <= 4; s++) {
#pragma unroll
            for (int a = -1; a <= 1; a++) {
#pragma unroll
                for (int d = -1; d <= 1; d++) {
                    if (a == 0 && d == 0) continue;
                    acc[tap_idx(s,a,d)] += ee * hp[a*s*HWD + d*s];
                }
            }
        }
    }

    const size_t base = ((size_t)(chunk*NB + b)*NK)*PLANE + gy*HDIM + gx;
#pragma unroll
    for (int k = 0; k < NK; k++)
        g_Ap[base + (size_t)k*PLANE] = acc[k];
}

__global__ void __launch_bounds__(256) softmax_kernel()
{
    const int g = blockIdx.x*256 + threadIdx.x;
    const int b = g / PLANE;
    const int p = g - b*PLANE;
    const int py = p / HDIM, px = p - py*HDIM;

    float a[NK];
#pragma unroll
    for (int k = 0; k < NK; k++) a[k] = 0.f;
#pragma unroll
    for (int ch = 0; ch < CSPLIT; ch++) {
        const size_t base = ((size_t)(ch*NB + b)*NK)*PLANE + p;
#pragma unroll
        for (int k = 0; k < NK; k++)
            a[k] += g_Ap[base + (size_t)k*PLANE];
    }

#pragma unroll
    for (int s = 1; s <= 4; s++) {
#pragma unroll
        for (int aa = -1; aa <= 1; aa++) {
#pragma unroll
            for (int d = -1; d <= 1; d++) {
                if (aa == 0 && d == 0) continue;
                const int yy = py + aa*s, xx = px + d*s;
                if (!(((unsigned)yy < HDIM) && ((unsigned)xx < HDIM)))
                    a[tap_idx(s,aa,d)] = -1e30f;
            }
        }
    }
    float m = a[0];
#pragma unroll
    for (int k = 1; k < NK; k++) m = fmaxf(m, a[k]);
    float ssum = 0.f;
#pragma unroll
    for (int k = 0; k < NK; k++) { a[k] = __expf(a[k] - m); ssum += a[k]; }
    const float inv = 1.f / ssum;

    const size_t wbase = ((size_t)b*NK)*PLANE + p;
#pragma unroll
    for (int k = 0; k < NK; k++)
        g_Wt[wbase + (size_t)k*PLANE] = a[k] * inv;
}

__global__ void __launch_bounds__(256) gather_kernel(
    const float* __restrict__ Ft, float* __restrict__ out)
{
    __shared__ float st[NSTAGE][HSZ];

    const int z     = blockIdx.z;
    const int b     = z & (NB - 1);
    const int chunk = z >> 2;
    const int c0    = chunk * CPC;

    const int ty0 = blockIdx.y * TH;
    const int tx0 = blockIdx.x * TW;
    const int tid = threadIdx.x;
    const int lx = tid & 31, ly = tid >> 5;
    const int gy = ty0 + ly, gx = tx0 + lx;
    const int hy0 = ty0 - HA, hx0 = tx0 - HA;

    const float* __restrict__ Fb = Ft + (size_t)b * CHW;
    float* __restrict__ Outb     = out + (size_t)b * CHW;

    float w[NK];
    {
        const size_t wbase = ((size_t)b*NK)*PLANE + gy*HDIM + gx;
#pragma unroll
        for (int k = 0; k < NK; k++)
            w[k] = __ldg(&g_Wt[wbase + (size_t)k*PLANE]);
    }

    int srcOff[3], vb[3];
#pragma unroll
    for (int j = 0; j < 3; j++) {
        const int i = tid + j*256;
        if (i < HSZ) {
            const int yy = i / HWD, xx = i - yy*HWD;
            const int py = hy0 + yy, px = hx0 + xx;
            const bool valid = ((unsigned)py < HDIM) && ((unsigned)px < HDIM);
            const int pyc = min(max(py, 0), HDIM-1);
            const int pxc = min(max(px, 0), HDIM-1);
            srcOff[j] = pyc*HDIM + pxc;
            vb[j] = valid ? 4 : 0;
        } else vb[j] = -1;
    }

    auto issue = [&](int c, int s){
#pragma unroll
        for (int j = 0; j < 3; j++) {
            if (vb[j] >= 0)
                cpa4(smaddr(&st[s][tid + j*256]), Fb + (size_t)c*PLANE + srcOff[j], vb[j]);
        }
        CP_COMMIT();
    };

    issue(c0 + 0, 0);
    issue(c0 + 1, 1);
    issue(c0 + 2, 2);

    const int obase = gy*HDIM + gx;
    for (int c = 0; c < CPC; c++) {
        CP_WAIT(2);
        __syncthreads();
        if (c + 3 < CPC) issue(c0 + c + 3, (c + 3) & (NSTAGE-1));
        else CP_COMMIT();

        const int buf = c & (NSTAGE-1);
        const float* hp = &st[buf][(ly + HA)*HWD + (lx + HA)];
        float o = w[0] * hp[0];
#pragma unroll
        for (int s = 1; s <= 4; s++) {
#pragma unroll
            for (int a = -1; a <= 1; a++) {
#pragma unroll
                for (int d = -1; d <= 1; d++) {
                    if (a == 0 && d == 0) continue;
                    o += w[tap_idx(s,a,d)] * hp[a*s*HWD + d*s];
                }
            }
        }
        Outb[(size_t)(c0 + c)*PLANE + obase] = o;
    }
}

// =====================================================================
extern "C" void kernel_launch(void* const* d_in, const int* in_sizes, int n_in,
                              void* d_out, int out_size)
{
    const float* Ft  = (const float*)d_in[0];
    const float* Fte = (const float*)d_in[1];
    const float* Wf  = (const float*)d_in[2];
    const float* bf  = (const float*)d_in[3];
    const float* Wg  = (const float*)d_in[4];
    const float* bg  = (const float*)d_in[5];
    float* out = (float*)d_out;

    split_w<<<512, 256>>>(Wf, Wg);
    dim3 gs(PLANE/32, CH/32, 8);                 // (288, 8, 8)
    split_x<<<gs, 256>>>(Ft, Fte);

    dim3 gg(PLANE/128, CH/128, NB*2);            // (72, 2, 8)
    gemm_mma<<<gg, 256>>>(bf, bg);

    dim3 g2(HDIM / TW, HDIM / TH, NB * CSPLIT);  // (3, 12, 16)
    affinity_kernel<<<g2, 256>>>();
    softmax_kernel<<<NB*PLANE/256, 256>>>();
    gather_kernel<<<g2, 256>>>(Ft, out);
}